// round 15
// baseline (speedup 1.0000x reference)
#include <cuda_runtime.h>
#include <cuda_bf16.h>

#define TPB    256
#define NBLK   592             // 148 SMs * 4 CTAs
#define EBLK   148             // event blocks: one per SM; then they help with pairs
#define NQ     10
#define EPSF   1e-12f
#define L2E    1.4426950408889634f
#define MAXPTS 2048

__device__ float2       g_partials[NBLK];
__device__ unsigned int g_sem = 0;   // self-resetting via atomicInc wrap

__device__ __forceinline__ float fsqrt_approx(float s) {
    float d; asm("sqrt.approx.f32 %0, %1;" : "=f"(d) : "f"(s)); return d;
}
__device__ __forceinline__ float fex2_approx(float a) {
    float e; asm("ex2.approx.f32 %0, %1;" : "=f"(e) : "f"(a)); return e;
}

// ---- shared epilogue: block reduce + last-block global reduce ----
__device__ __forceinline__ void block_and_grid_reduce(
    float acc_d, float acc_e, float beta, float t0, float tn,
    int n_events, float* __restrict__ out)
{
    #pragma unroll
    for (int o = 16; o > 0; o >>= 1) {
        acc_d += __shfl_down_sync(0xffffffffu, acc_d, o);
        acc_e += __shfl_down_sync(0xffffffffu, acc_e, o);
    }
    __shared__ float2 wred[TPB / 32];
    if ((threadIdx.x & 31) == 0)
        wred[threadIdx.x >> 5] = make_float2(acc_d, acc_e);
    __syncthreads();

    __shared__ bool is_last;
    if (threadIdx.x == 0) {
        float sd = 0.0f, se = 0.0f;
        #pragma unroll
        for (int w = 0; w < TPB / 32; w++) { sd += wred[w].x; se += wred[w].y; }
        g_partials[blockIdx.x] = make_float2(sd, se);
        __threadfence();
        unsigned old = atomicInc(&g_sem, gridDim.x - 1);
        is_last = (old == gridDim.x - 1);
    }
    __syncthreads();

    if (is_last) {
        double sd = 0.0, se = 0.0;
        const volatile float2* gp = (const volatile float2*)g_partials;
        for (int i = threadIdx.x; i < (int)gridDim.x; i += TPB) {
            sd += (double)gp[i].x;
            se += (double)gp[i].y;
        }
        #pragma unroll
        for (int o = 16; o > 0; o >>= 1) {
            sd += __shfl_down_sync(0xffffffffu, sd, o);
            se += __shfl_down_sync(0xffffffffu, se, o);
        }
        __shared__ double2 dred[TPB / 32];
        if ((threadIdx.x & 31) == 0)
            dred[threadIdx.x >> 5] = make_double2(sd, se);
        __syncthreads();
        if (threadIdx.x == 0) {
            double tsd = 0.0, tse = 0.0;
            #pragma unroll
            for (int w = 0; w < TPB / 32; w++) { tsd += dred[w].x; tse += dred[w].y; }
            double dtqD = ((double)tn - (double)t0) / (double)NQ;
            out[0] = (float)((double)beta * (double)n_events - tsd - dtqD * tse);
        }
    }
}

// ---- pair slice worker: 3-chain EX2 body over [base, base+count) ----
__device__ __forceinline__ float pair_slice(
    const float4* __restrict__ sm,
    const int* __restrict__ pair_u, const int* __restrict__ pair_v,
    int base, int count, int tid, int stride, int is_lead_block,
    float t05, float dtq, float bL2E)
{
    const int n3 = count / 3;
    float eA = 0.0f, eB = 0.0f, eC = 0.0f;
    for (int idx = tid; idx < n3; idx += stride) {
        int kA = base + idx, kB = kA + n3, kC = kB + n3;
        float4 aA = sm[pair_u[kA]], bA = sm[pair_v[kA]];
        float4 aB = sm[pair_u[kB]], bB = sm[pair_v[kB]];
        float4 aC = sm[pair_u[kC]], bC = sm[pair_v[kC]];

        float dxA = aA.x - bA.x, dyA = aA.y - bA.y;
        float vxA = aA.z - bA.z, vyA = aA.w - bA.w;
        float cA0 = fmaf(dxA, dxA, fmaf(dyA, dyA, EPSF));
        float cA1 = 2.0f * fmaf(dxA, vxA, dyA * vyA);
        float cA2 = fmaf(vxA, vxA, vyA * vyA);

        float dxB = aB.x - bB.x, dyB = aB.y - bB.y;
        float vxB = aB.z - bB.z, vyB = aB.w - bB.w;
        float cB0 = fmaf(dxB, dxB, fmaf(dyB, dyB, EPSF));
        float cB1 = 2.0f * fmaf(dxB, vxB, dyB * vyB);
        float cB2 = fmaf(vxB, vxB, vyB * vyB);

        float dxC = aC.x - bC.x, dyC = aC.y - bC.y;
        float vxC = aC.z - bC.z, vyC = aC.w - bC.w;
        float cC0 = fmaf(dxC, dxC, fmaf(dyC, dyC, EPSF));
        float cC1 = 2.0f * fmaf(dxC, vxC, dyC * vyC);
        float cC2 = fmaf(vxC, vxC, vyC * vyC);

        float t = t05;
        #pragma unroll
        for (int q = 0; q < NQ; q++) {
            float sA = fmaxf(fmaf(fmaf(cA2, t, cA1), t, cA0), EPSF);
            float sB = fmaxf(fmaf(fmaf(cB2, t, cB1), t, cB0), EPSF);
            float sC = fmaxf(fmaf(fmaf(cC2, t, cC1), t, cC0), EPSF);
            float dA = fsqrt_approx(sA);
            float dB = fsqrt_approx(sB);
            float dC = fsqrt_approx(sC);
            eA += fex2_approx(fmaf(dA, -L2E, bL2E));
            eB += fex2_approx(fmaf(dB, -L2E, bL2E));
            eC += fex2_approx(fmaf(dC, -L2E, bL2E));
            t += dtq;
        }
    }
    // leftover pairs [base+3*n3, base+count): at most 2, lead block's first lanes
    int left0 = base + 3 * n3;
    int nleft = (base + count) - left0;
    if (is_lead_block && (int)threadIdx.x < nleft) {
        int k = left0 + threadIdx.x;
        float4 a = sm[pair_u[k]], b = sm[pair_v[k]];
        float dx = a.x - b.x, dy = a.y - b.y;
        float vx = a.z - b.z, vy = a.w - b.w;
        float c0 = fmaf(dx, dx, fmaf(dy, dy, EPSF));
        float c1 = 2.0f * fmaf(dx, vx, dy * vy);
        float c2 = fmaf(vx, vx, vy * vy);
        float t = t05;
        #pragma unroll
        for (int q = 0; q < NQ; q++) {
            float s = fmaxf(fmaf(fmaf(c2, t, c1), t, c0), EPSF);
            eA += fex2_approx(fmaf(fsqrt_approx(s), -L2E, bL2E));
            t += dtq;
        }
    }
    return (eA + eB) + eC;
}

__global__ __launch_bounds__(TPB, 4) void cvm_coop_kernel(
    const float* __restrict__ z0, const float* __restrict__ v0,
    const float* __restrict__ beta_p, const float* __restrict__ data_t,
    const float* __restrict__ t0_p, const float* __restrict__ tn_p,
    const int2* __restrict__ data_uv,
    const int* __restrict__ pair_u, const int* __restrict__ pair_v,
    int n_points, int n_events, int n_pairs, int psplit,
    float* __restrict__ out)
{
    __shared__ float4 sm[MAXPTS];
    {
        const float2* z2 = (const float2*)z0;
        const float2* v2 = (const float2*)v0;
        for (int i = threadIdx.x; i < n_points; i += TPB) {
            float2 z = z2[i];
            float2 v = v2[i];
            sm[i] = make_float4(z.x, z.y, v.x, v.y);
        }
    }
    __syncthreads();

    const float beta = *beta_p;
    const float t0   = *t0_p;
    const float tn   = *tn_p;
    const float dtq  = (tn - t0) * (1.0f / NQ);
    const float t05  = t0 + 0.5f * dtq;
    const float bL2E = beta * L2E;

    float acc_d = 0.0f, acc_e = 0.0f;

    if (blockIdx.x < EBLK) {
        // ========== EVENT BLOCKS: events first, then pair slice [0, psplit) =====
        const int tid    = blockIdx.x * TPB + threadIdx.x;
        const int stride = EBLK * TPB;
        {
            const int4*   uv4 = (const int4*)data_uv;
            const float4* tt4 = (const float4*)data_t;
            const int nev4 = n_events >> 2;
            for (int i = tid; i < nev4; i += stride) {
                int4   qa = uv4[2 * i];
                int4   qb = uv4[2 * i + 1];
                float4 tt = tt4[i];
                float4 a0 = sm[qa.x], b0 = sm[qa.y];
                float4 a1 = sm[qa.z], b1 = sm[qa.w];
                float4 a2 = sm[qb.x], b2 = sm[qb.y];
                float4 a3 = sm[qb.z], b3 = sm[qb.w];
                float dx0 = fmaf(a0.z - b0.z, tt.x, a0.x - b0.x);
                float dy0 = fmaf(a0.w - b0.w, tt.x, a0.y - b0.y);
                float dx1 = fmaf(a1.z - b1.z, tt.y, a1.x - b1.x);
                float dy1 = fmaf(a1.w - b1.w, tt.y, a1.y - b1.y);
                float dx2 = fmaf(a2.z - b2.z, tt.z, a2.x - b2.x);
                float dy2 = fmaf(a2.w - b2.w, tt.z, a2.y - b2.y);
                float dx3 = fmaf(a3.z - b3.z, tt.w, a3.x - b3.x);
                float dy3 = fmaf(a3.w - b3.w, tt.w, a3.y - b3.y);
                acc_d += fsqrt_approx(fmaf(dx0, dx0, fmaf(dy0, dy0, EPSF)));
                acc_d += fsqrt_approx(fmaf(dx1, dx1, fmaf(dy1, dy1, EPSF)));
                acc_d += fsqrt_approx(fmaf(dx2, dx2, fmaf(dy2, dy2, EPSF)));
                acc_d += fsqrt_approx(fmaf(dx3, dx3, fmaf(dy3, dy3, EPSF)));
            }
            int tail0 = nev4 << 2;
            int ntail = n_events - tail0;
            if (blockIdx.x == 0 && threadIdx.x < (unsigned)ntail) {
                int   i  = tail0 + threadIdx.x;
                int2  uv = data_uv[i];
                float t  = data_t[i];
                float4 a = sm[uv.x], b = sm[uv.y];
                float dx = fmaf(a.z - b.z, t, a.x - b.x);
                float dy = fmaf(a.w - b.w, t, a.y - b.y);
                acc_d += fsqrt_approx(fmaf(dx, dx, fmaf(dy, dy, EPSF)));
            }
        }
        // pair slice A
        acc_e = pair_slice(sm, pair_u, pair_v, 0, psplit,
                           tid, stride, blockIdx.x == 0, t05, dtq, bL2E);
    } else {
        // ========== PAIR BLOCKS: slice [psplit, n_pairs) ==========
        const int tid    = (blockIdx.x - EBLK) * TPB + threadIdx.x;
        const int stride = (NBLK - EBLK) * TPB;
        acc_e = pair_slice(sm, pair_u, pair_v, psplit, n_pairs - psplit,
                           tid, stride, blockIdx.x == EBLK, t05, dtq, bL2E);
    }

    block_and_grid_reduce(acc_d, acc_e, beta, t0, tn, n_events, out);
}

extern "C" void kernel_launch(void* const* d_in, const int* in_sizes, int n_in,
                              void* d_out, int out_size)
{
    // metadata order: z0, v0, beta, data_t, t0, tn, data_uv, pair_u, pair_v
    const float* z0      = (const float*)d_in[0];
    const float* v0      = (const float*)d_in[1];
    const float* beta_p  = (const float*)d_in[2];
    const float* data_t  = (const float*)d_in[3];
    const float* t0_p    = (const float*)d_in[4];
    const float* tn_p    = (const float*)d_in[5];
    const int2*  data_uv = (const int2*)d_in[6];
    const int*   pair_u  = (const int*)d_in[7];
    const int*   pair_v  = (const int*)d_in[8];
    float* out = (float*)d_out;

    int n_points = in_sizes[0] / 2;
    int n_events = in_sizes[3];
    int n_pairs  = in_sizes[7];

    // static cooperative split: event blocks take ~16% of pair work after events
    int psplit = (int)((long long)n_pairs * 16 / 100);

    cvm_coop_kernel<<<NBLK, TPB>>>(z0, v0, beta_p, data_t, t0_p, tn_p,
                                   data_uv, pair_u, pair_v,
                                   n_points, n_events, n_pairs, psplit, out);
}

// round 16
// speedup vs baseline: 1.0816x; 1.0816x over previous
#include <cuda_runtime.h>
#include <cuda_bf16.h>

#define TPB    256
#define NBLK   592             // 148 SMs * 4 CTAs
#define EBLK   68              // balance point from measured linear model
#define NQ     10
#define EPSF   1e-12f
#define L2E    1.4426950408889634f
#define MAXPTS 2048

__device__ float2       g_partials[NBLK];
__device__ unsigned int g_sem = 0;   // self-resetting via atomicInc wrap

__device__ __forceinline__ float fsqrt_approx(float s) {
    float d; asm("sqrt.approx.f32 %0, %1;" : "=f"(d) : "f"(s)); return d;
}
__device__ __forceinline__ float fex2_approx(float a) {
    float e; asm("ex2.approx.f32 %0, %1;" : "=f"(e) : "f"(a)); return e;
}

// ---- shared epilogue: block reduce + last-block global reduce ----
__device__ __forceinline__ void block_and_grid_reduce(
    float acc_d, float acc_e, float beta, float t0, float tn,
    int n_events, float* __restrict__ out)
{
    #pragma unroll
    for (int o = 16; o > 0; o >>= 1) {
        acc_d += __shfl_down_sync(0xffffffffu, acc_d, o);
        acc_e += __shfl_down_sync(0xffffffffu, acc_e, o);
    }
    __shared__ float2 wred[TPB / 32];
    if ((threadIdx.x & 31) == 0)
        wred[threadIdx.x >> 5] = make_float2(acc_d, acc_e);
    __syncthreads();

    __shared__ bool is_last;
    if (threadIdx.x == 0) {
        float sd = 0.0f, se = 0.0f;
        #pragma unroll
        for (int w = 0; w < TPB / 32; w++) { sd += wred[w].x; se += wred[w].y; }
        g_partials[blockIdx.x] = make_float2(sd, se);
        __threadfence();
        unsigned old = atomicInc(&g_sem, gridDim.x - 1);
        is_last = (old == gridDim.x - 1);
    }
    __syncthreads();

    if (is_last) {
        double sd = 0.0, se = 0.0;
        const volatile float2* gp = (const volatile float2*)g_partials;
        for (int i = threadIdx.x; i < (int)gridDim.x; i += TPB) {
            sd += (double)gp[i].x;
            se += (double)gp[i].y;
        }
        #pragma unroll
        for (int o = 16; o > 0; o >>= 1) {
            sd += __shfl_down_sync(0xffffffffu, sd, o);
            se += __shfl_down_sync(0xffffffffu, se, o);
        }
        __shared__ double2 dred[TPB / 32];
        if ((threadIdx.x & 31) == 0)
            dred[threadIdx.x >> 5] = make_double2(sd, se);
        __syncthreads();
        if (threadIdx.x == 0) {
            double tsd = 0.0, tse = 0.0;
            #pragma unroll
            for (int w = 0; w < TPB / 32; w++) { tsd += dred[w].x; tse += dred[w].y; }
            double dtqD = ((double)tn - (double)t0) / (double)NQ;
            out[0] = (float)((double)beta * (double)n_events - tsd - dtqD * tse);
        }
    }
}

__global__ __launch_bounds__(TPB, 4) void cvm_split_kernel(
    const float* __restrict__ z0, const float* __restrict__ v0,
    const float* __restrict__ beta_p, const float* __restrict__ data_t,
    const float* __restrict__ t0_p, const float* __restrict__ tn_p,
    const int2* __restrict__ data_uv,
    const int* __restrict__ pair_u, const int* __restrict__ pair_v,
    int n_points, int n_events, int n_pairs,
    float* __restrict__ out)
{
    __shared__ float4 sm[MAXPTS];
    {
        const float2* z2 = (const float2*)z0;
        const float2* v2 = (const float2*)v0;
        for (int i = threadIdx.x; i < n_points; i += TPB) {
            float2 z = z2[i];
            float2 v = v2[i];
            sm[i] = make_float4(z.x, z.y, v.x, v.y);
        }
    }
    __syncthreads();

    const float beta = *beta_p;
    const float t0   = *t0_p;
    const float tn   = *tn_p;
    const float dtq  = (tn - t0) * (1.0f / NQ);
    const float t05  = t0 + 0.5f * dtq;
    const float bL2E = beta * L2E;

    float acc_d = 0.0f, acc_e = 0.0f;

    if (blockIdx.x < EBLK) {
        // ===== EVENT ROLE: 4 events/iter, software-pipelined prefetch =====
        const int tid    = blockIdx.x * TPB + threadIdx.x;
        const int stride = EBLK * TPB;
        const int4*   uv4 = (const int4*)data_uv;
        const float4* tt4 = (const float4*)data_t;
        const int nev4 = n_events >> 2;

        int i = tid;
        if (i < nev4) {
            int4   qa = uv4[2 * i];
            int4   qb = uv4[2 * i + 1];
            float4 tt = tt4[i];
            while (true) {
                // prefetch next iteration's streams (flies during gather+sqrt below)
                int inext = i + stride;
                bool has = inext < nev4;
                int4 qa2, qb2; float4 tt2;
                if (has) {
                    qa2 = uv4[2 * inext];
                    qb2 = uv4[2 * inext + 1];
                    tt2 = tt4[inext];
                }
                // process current
                float4 a0 = sm[qa.x], b0 = sm[qa.y];
                float4 a1 = sm[qa.z], b1 = sm[qa.w];
                float4 a2 = sm[qb.x], b2 = sm[qb.y];
                float4 a3 = sm[qb.z], b3 = sm[qb.w];
                float dx0 = fmaf(a0.z - b0.z, tt.x, a0.x - b0.x);
                float dy0 = fmaf(a0.w - b0.w, tt.x, a0.y - b0.y);
                float dx1 = fmaf(a1.z - b1.z, tt.y, a1.x - b1.x);
                float dy1 = fmaf(a1.w - b1.w, tt.y, a1.y - b1.y);
                float dx2 = fmaf(a2.z - b2.z, tt.z, a2.x - b2.x);
                float dy2 = fmaf(a2.w - b2.w, tt.z, a2.y - b2.y);
                float dx3 = fmaf(a3.z - b3.z, tt.w, a3.x - b3.x);
                float dy3 = fmaf(a3.w - b3.w, tt.w, a3.y - b3.y);
                acc_d += fsqrt_approx(fmaf(dx0, dx0, fmaf(dy0, dy0, EPSF)));
                acc_d += fsqrt_approx(fmaf(dx1, dx1, fmaf(dy1, dy1, EPSF)));
                acc_d += fsqrt_approx(fmaf(dx2, dx2, fmaf(dy2, dy2, EPSF)));
                acc_d += fsqrt_approx(fmaf(dx3, dx3, fmaf(dy3, dy3, EPSF)));
                if (!has) break;
                i = inext; qa = qa2; qb = qb2; tt = tt2;
            }
        }
        // tail events [nev4*4, n_events)
        int tail0 = nev4 << 2;
        int ntail = n_events - tail0;
        if (blockIdx.x == 0 && (int)threadIdx.x < ntail) {
            int   k  = tail0 + threadIdx.x;
            int2  uv = data_uv[k];
            float t  = data_t[k];
            float4 a = sm[uv.x], b = sm[uv.y];
            float dx = fmaf(a.z - b.z, t, a.x - b.x);
            float dy = fmaf(a.w - b.w, t, a.y - b.y);
            acc_d += fsqrt_approx(fmaf(dx, dx, fmaf(dy, dy, EPSF)));
        }
    } else {
        // ================ PAIR ROLE: 3 chains (3-way index split) ===============
        const int tid    = (blockIdx.x - EBLK) * TPB + threadIdx.x;
        const int stride = (NBLK - EBLK) * TPB;
        const int np3 = n_pairs / 3;

        float eA = 0.0f, eB = 0.0f, eC = 0.0f;
        for (int idx = tid; idx < np3; idx += stride) {
            int kA = idx, kB = idx + np3, kC = idx + 2 * np3;
            int uA = pair_u[kA], vA = pair_v[kA];
            int uB = pair_u[kB], vB = pair_v[kB];
            int uC = pair_u[kC], vC = pair_v[kC];
            float4 aA = sm[uA], bA = sm[vA];
            float4 aB = sm[uB], bB = sm[vB];
            float4 aC = sm[uC], bC = sm[vC];

            float dxA = aA.x - bA.x, dyA = aA.y - bA.y;
            float vxA = aA.z - bA.z, vyA = aA.w - bA.w;
            float cA0 = fmaf(dxA, dxA, fmaf(dyA, dyA, EPSF));
            float cA1 = 2.0f * fmaf(dxA, vxA, dyA * vyA);
            float cA2 = fmaf(vxA, vxA, vyA * vyA);

            float dxB = aB.x - bB.x, dyB = aB.y - bB.y;
            float vxB = aB.z - bB.z, vyB = aB.w - bB.w;
            float cB0 = fmaf(dxB, dxB, fmaf(dyB, dyB, EPSF));
            float cB1 = 2.0f * fmaf(dxB, vxB, dyB * vyB);
            float cB2 = fmaf(vxB, vxB, vyB * vyB);

            float dxC = aC.x - bC.x, dyC = aC.y - bC.y;
            float vxC = aC.z - bC.z, vyC = aC.w - bC.w;
            float cC0 = fmaf(dxC, dxC, fmaf(dyC, dyC, EPSF));
            float cC1 = 2.0f * fmaf(dxC, vxC, dyC * vyC);
            float cC2 = fmaf(vxC, vxC, vyC * vyC);

            float t = t05;
            #pragma unroll
            for (int q = 0; q < NQ; q++) {
                float sA = fmaxf(fmaf(fmaf(cA2, t, cA1), t, cA0), EPSF);
                float sB = fmaxf(fmaf(fmaf(cB2, t, cB1), t, cB0), EPSF);
                float sC = fmaxf(fmaf(fmaf(cC2, t, cC1), t, cC0), EPSF);
                float dA = fsqrt_approx(sA);
                float dB = fsqrt_approx(sB);
                float dC = fsqrt_approx(sC);
                eA += fex2_approx(fmaf(dA, -L2E, bL2E));
                eB += fex2_approx(fmaf(dB, -L2E, bL2E));
                eC += fex2_approx(fmaf(dC, -L2E, bL2E));
                t += dtq;
            }
        }
        // leftover pairs [3*np3, n_pairs): at most 2
        int left0 = 3 * np3;
        int nleft = n_pairs - left0;
        if (blockIdx.x == EBLK && (int)threadIdx.x < nleft) {
            int k = left0 + threadIdx.x;
            float4 a = sm[pair_u[k]], b = sm[pair_v[k]];
            float dx = a.x - b.x, dy = a.y - b.y;
            float vx = a.z - b.z, vy = a.w - b.w;
            float c0 = fmaf(dx, dx, fmaf(dy, dy, EPSF));
            float c1 = 2.0f * fmaf(dx, vx, dy * vy);
            float c2 = fmaf(vx, vx, vy * vy);
            float t = t05;
            #pragma unroll
            for (int q = 0; q < NQ; q++) {
                float s = fmaxf(fmaf(fmaf(c2, t, c1), t, c0), EPSF);
                eA += fex2_approx(fmaf(fsqrt_approx(s), -L2E, bL2E));
                t += dtq;
            }
        }
        acc_e = (eA + eB) + eC;
    }

    block_and_grid_reduce(acc_d, acc_e, beta, t0, tn, n_events, out);
}

extern "C" void kernel_launch(void* const* d_in, const int* in_sizes, int n_in,
                              void* d_out, int out_size)
{
    // metadata order: z0, v0, beta, data_t, t0, tn, data_uv, pair_u, pair_v
    const float* z0      = (const float*)d_in[0];
    const float* v0      = (const float*)d_in[1];
    const float* beta_p  = (const float*)d_in[2];
    const float* data_t  = (const float*)d_in[3];
    const float* t0_p    = (const float*)d_in[4];
    const float* tn_p    = (const float*)d_in[5];
    const int2*  data_uv = (const int2*)d_in[6];
    const int*   pair_u  = (const int*)d_in[7];
    const int*   pair_v  = (const int*)d_in[8];
    float* out = (float*)d_out;

    int n_points = in_sizes[0] / 2;
    int n_events = in_sizes[3];
    int n_pairs  = in_sizes[7];

    cvm_split_kernel<<<NBLK, TPB>>>(z0, v0, beta_p, data_t, t0_p, tn_p,
                                    data_uv, pair_u, pair_v,
                                    n_points, n_events, n_pairs, out);
}

// round 17
// speedup vs baseline: 1.1664x; 1.0784x over previous
#include <cuda_runtime.h>
#include <cuda_bf16.h>

#define TPB    256
#define NBLK   592             // 148 SMs * 4 CTAs
#define EBLK   80              // proven optimum from EBLK scan {46,68,80,148}
#define NQ     10
#define EPSF   1e-12f
#define L2E    1.4426950408889634f
#define MAXPTS 2048

__device__ float2       g_partials[NBLK];
__device__ unsigned int g_sem = 0;   // self-resetting via atomicInc wrap

__device__ __forceinline__ float fsqrt_approx(float s) {
    float d; asm("sqrt.approx.f32 %0, %1;" : "=f"(d) : "f"(s)); return d;
}
__device__ __forceinline__ float fex2_approx(float a) {
    float e; asm("ex2.approx.f32 %0, %1;" : "=f"(e) : "f"(a)); return e;
}

// ---- shared epilogue: block reduce + last-block global reduce ----
__device__ __forceinline__ void block_and_grid_reduce(
    float acc_d, float acc_e, float beta, float t0, float tn,
    int n_events, float* __restrict__ out)
{
    #pragma unroll
    for (int o = 16; o > 0; o >>= 1) {
        acc_d += __shfl_down_sync(0xffffffffu, acc_d, o);
        acc_e += __shfl_down_sync(0xffffffffu, acc_e, o);
    }
    __shared__ float2 wred[TPB / 32];
    if ((threadIdx.x & 31) == 0)
        wred[threadIdx.x >> 5] = make_float2(acc_d, acc_e);
    __syncthreads();

    __shared__ bool is_last;
    if (threadIdx.x == 0) {
        float sd = 0.0f, se = 0.0f;
        #pragma unroll
        for (int w = 0; w < TPB / 32; w++) { sd += wred[w].x; se += wred[w].y; }
        g_partials[blockIdx.x] = make_float2(sd, se);
        __threadfence();
        unsigned old = atomicInc(&g_sem, gridDim.x - 1);
        is_last = (old == gridDim.x - 1);
    }
    __syncthreads();

    if (is_last) {
        double sd = 0.0, se = 0.0;
        const volatile float2* gp = (const volatile float2*)g_partials;
        for (int i = threadIdx.x; i < (int)gridDim.x; i += TPB) {
            sd += (double)gp[i].x;
            se += (double)gp[i].y;
        }
        #pragma unroll
        for (int o = 16; o > 0; o >>= 1) {
            sd += __shfl_down_sync(0xffffffffu, sd, o);
            se += __shfl_down_sync(0xffffffffu, se, o);
        }
        __shared__ double2 dred[TPB / 32];
        if ((threadIdx.x & 31) == 0)
            dred[threadIdx.x >> 5] = make_double2(sd, se);
        __syncthreads();
        if (threadIdx.x == 0) {
            double tsd = 0.0, tse = 0.0;
            #pragma unroll
            for (int w = 0; w < TPB / 32; w++) { tsd += dred[w].x; tse += dred[w].y; }
            double dtqD = ((double)tn - (double)t0) / (double)NQ;
            out[0] = (float)((double)beta * (double)n_events - tsd - dtqD * tse);
        }
    }
}

__global__ __launch_bounds__(TPB, 4) void cvm_split_kernel(
    const float* __restrict__ z0, const float* __restrict__ v0,
    const float* __restrict__ beta_p, const float* __restrict__ data_t,
    const float* __restrict__ t0_p, const float* __restrict__ tn_p,
    const int2* __restrict__ data_uv,
    const int* __restrict__ pair_u, const int* __restrict__ pair_v,
    int n_points, int n_events, int n_pairs,
    float* __restrict__ out)
{
    __shared__ float4 sm[MAXPTS];
    {
        const float2* z2 = (const float2*)z0;
        const float2* v2 = (const float2*)v0;
        for (int i = threadIdx.x; i < n_points; i += TPB) {
            float2 z = z2[i];
            float2 v = v2[i];
            sm[i] = make_float4(z.x, z.y, v.x, v.y);
        }
    }
    __syncthreads();

    const float beta = *beta_p;
    const float t0   = *t0_p;
    const float tn   = *tn_p;
    const float dtq  = (tn - t0) * (1.0f / NQ);
    const float t05  = t0 + 0.5f * dtq;
    const float bL2E = beta * L2E;

    float acc_d = 0.0f, acc_e = 0.0f;

    if (blockIdx.x < EBLK) {
        // ================= EVENT ROLE: 4 events / iter (R8-exact) ==============
        const int tid    = blockIdx.x * TPB + threadIdx.x;
        const int stride = EBLK * TPB;
        const int4*   uv4 = (const int4*)data_uv;
        const float4* tt4 = (const float4*)data_t;
        const int nev4 = n_events >> 2;
        for (int i = tid; i < nev4; i += stride) {
            int4   qa = uv4[2 * i];
            int4   qb = uv4[2 * i + 1];
            float4 tt = tt4[i];
            float4 a0 = sm[qa.x], b0 = sm[qa.y];
            float4 a1 = sm[qa.z], b1 = sm[qa.w];
            float4 a2 = sm[qb.x], b2 = sm[qb.y];
            float4 a3 = sm[qb.z], b3 = sm[qb.w];
            float dx0 = fmaf(a0.z - b0.z, tt.x, a0.x - b0.x);
            float dy0 = fmaf(a0.w - b0.w, tt.x, a0.y - b0.y);
            float dx1 = fmaf(a1.z - b1.z, tt.y, a1.x - b1.x);
            float dy1 = fmaf(a1.w - b1.w, tt.y, a1.y - b1.y);
            float dx2 = fmaf(a2.z - b2.z, tt.z, a2.x - b2.x);
            float dy2 = fmaf(a2.w - b2.w, tt.z, a2.y - b2.y);
            float dx3 = fmaf(a3.z - b3.z, tt.w, a3.x - b3.x);
            float dy3 = fmaf(a3.w - b3.w, tt.w, a3.y - b3.y);
            acc_d += fsqrt_approx(fmaf(dx0, dx0, fmaf(dy0, dy0, EPSF)));
            acc_d += fsqrt_approx(fmaf(dx1, dx1, fmaf(dy1, dy1, EPSF)));
            acc_d += fsqrt_approx(fmaf(dx2, dx2, fmaf(dy2, dy2, EPSF)));
            acc_d += fsqrt_approx(fmaf(dx3, dx3, fmaf(dy3, dy3, EPSF)));
        }
        int tail0 = nev4 << 2;
        int ntail = n_events - tail0;
        if (blockIdx.x == 0 && (int)threadIdx.x < ntail) {
            int   i  = tail0 + threadIdx.x;
            int2  uv = data_uv[i];
            float t  = data_t[i];
            float4 a = sm[uv.x], b = sm[uv.y];
            float dx = fmaf(a.z - b.z, t, a.x - b.x);
            float dy = fmaf(a.w - b.w, t, a.y - b.y);
            acc_d += fsqrt_approx(fmaf(dx, dx, fmaf(dy, dy, EPSF)));
        }
    } else {
        // ===== PAIR ROLE: 3 chains, software-pipelined index loads =====
        const int tid    = (blockIdx.x - EBLK) * TPB + threadIdx.x;
        const int stride = (NBLK - EBLK) * TPB;
        const int np3 = n_pairs / 3;

        float eA = 0.0f, eB = 0.0f, eC = 0.0f;

        int idx = tid;
        if (idx < np3) {
            // prologue: load current indices
            int uA = pair_u[idx],           vA = pair_v[idx];
            int uB = pair_u[idx + np3],     vB = pair_v[idx + np3];
            int uC = pair_u[idx + 2 * np3], vC = pair_v[idx + 2 * np3];
            while (true) {
                // prefetch next iteration's indices (clamped; always safe)
                int nidx = idx + stride;
                bool has = nidx < np3;
                int cidx = has ? nidx : idx;
                int uA2 = pair_u[cidx],           vA2 = pair_v[cidx];
                int uB2 = pair_u[cidx + np3],     vB2 = pair_v[cidx + np3];
                int uC2 = pair_u[cidx + 2 * np3], vC2 = pair_v[cidx + 2 * np3];

                // body on current indices
                float4 aA = sm[uA], bA = sm[vA];
                float4 aB = sm[uB], bB = sm[vB];
                float4 aC = sm[uC], bC = sm[vC];

                float dxA = aA.x - bA.x, dyA = aA.y - bA.y;
                float vxA = aA.z - bA.z, vyA = aA.w - bA.w;
                float cA0 = fmaf(dxA, dxA, fmaf(dyA, dyA, EPSF));
                float cA1 = 2.0f * fmaf(dxA, vxA, dyA * vyA);
                float cA2 = fmaf(vxA, vxA, vyA * vyA);

                float dxB = aB.x - bB.x, dyB = aB.y - bB.y;
                float vxB = aB.z - bB.z, vyB = aB.w - bB.w;
                float cB0 = fmaf(dxB, dxB, fmaf(dyB, dyB, EPSF));
                float cB1 = 2.0f * fmaf(dxB, vxB, dyB * vyB);
                float cB2 = fmaf(vxB, vxB, vyB * vyB);

                float dxC = aC.x - bC.x, dyC = aC.y - bC.y;
                float vxC = aC.z - bC.z, vyC = aC.w - bC.w;
                float cC0 = fmaf(dxC, dxC, fmaf(dyC, dyC, EPSF));
                float cC1 = 2.0f * fmaf(dxC, vxC, dyC * vyC);
                float cC2 = fmaf(vxC, vxC, vyC * vyC);

                #pragma unroll
                for (int q = 0; q < NQ; q++) {
                    float t  = fmaf((float)q, dtq, t05);   // independent per q
                    float sA = fmaxf(fmaf(fmaf(cA2, t, cA1), t, cA0), EPSF);
                    float sB = fmaxf(fmaf(fmaf(cB2, t, cB1), t, cB0), EPSF);
                    float sC = fmaxf(fmaf(fmaf(cC2, t, cC1), t, cC0), EPSF);
                    float dA = fsqrt_approx(sA);
                    float dB = fsqrt_approx(sB);
                    float dC = fsqrt_approx(sC);
                    eA += fex2_approx(fmaf(dA, -L2E, bL2E));
                    eB += fex2_approx(fmaf(dB, -L2E, bL2E));
                    eC += fex2_approx(fmaf(dC, -L2E, bL2E));
                }

                if (!has) break;
                idx = nidx;
                uA = uA2; vA = vA2; uB = uB2; vB = vB2; uC = uC2; vC = vC2;
            }
        }
        // leftover pairs [3*np3, n_pairs): at most 2
        int left0 = 3 * np3;
        int nleft = n_pairs - left0;
        if (blockIdx.x == EBLK && (int)threadIdx.x < nleft) {
            int k = left0 + threadIdx.x;
            float4 a = sm[pair_u[k]], b = sm[pair_v[k]];
            float dx = a.x - b.x, dy = a.y - b.y;
            float vx = a.z - b.z, vy = a.w - b.w;
            float c0 = fmaf(dx, dx, fmaf(dy, dy, EPSF));
            float c1 = 2.0f * fmaf(dx, vx, dy * vy);
            float c2 = fmaf(vx, vx, vy * vy);
            #pragma unroll
            for (int q = 0; q < NQ; q++) {
                float t = fmaf((float)q, dtq, t05);
                float s = fmaxf(fmaf(fmaf(c2, t, c1), t, c0), EPSF);
                eA += fex2_approx(fmaf(fsqrt_approx(s), -L2E, bL2E));
            }
        }
        acc_e = (eA + eB) + eC;
    }

    block_and_grid_reduce(acc_d, acc_e, beta, t0, tn, n_events, out);
}

extern "C" void kernel_launch(void* const* d_in, const int* in_sizes, int n_in,
                              void* d_out, int out_size)
{
    // metadata order: z0, v0, beta, data_t, t0, tn, data_uv, pair_u, pair_v
    const float* z0      = (const float*)d_in[0];
    const float* v0      = (const float*)d_in[1];
    const float* beta_p  = (const float*)d_in[2];
    const float* data_t  = (const float*)d_in[3];
    const float* t0_p    = (const float*)d_in[4];
    const float* tn_p    = (const float*)d_in[5];
    const int2*  data_uv = (const int2*)d_in[6];
    const int*   pair_u  = (const int*)d_in[7];
    const int*   pair_v  = (const int*)d_in[8];
    float* out = (float*)d_out;

    int n_points = in_sizes[0] / 2;
    int n_events = in_sizes[3];
    int n_pairs  = in_sizes[7];

    cvm_split_kernel<<<NBLK, TPB>>>(z0, v0, beta_p, data_t, t0_p, tn_p,
                                    data_uv, pair_u, pair_v,
                                    n_points, n_events, n_pairs, out);
}